// round 11
// baseline (speedup 1.0000x reference)
#include <cuda_runtime.h>
#include <math_constants.h>
#include <cstdint>

// ChamferDistanceLoss, B=8, N=4096, D=3 — fused both directions.
// d(i,j) = rn_i + cn_j - 2 p1_i.p2_j computed ONCE per pair.
// Cross-tile min reduction via deterministic atomicMax on a monotone unsigned
// key (min over floats == max over keys; exact, order-independent; key 0 is
// the identity, matching zero-initialized / post-reset buffers).

#define NPTS 4096
#define BATCH 8
#define RPB 128
#define CPB 1024
#define RT 32
#define CT 4
#define MAIN_BLOCKS (BATCH * RT * CT)       // 1024
#define THREADS 128
#define NWARPS 4
#define WCOLS (CPB / NWARPS)                // 256
#define FIN_THREADS 256
#define FIN_BLOCKS (BATCH * NPTS / FIN_THREADS)  // 128

__device__ unsigned int g_rowkey[BATCH * NPTS];   // 128 KB, zero = identity
__device__ unsigned int g_colkey[BATCH * NPTS];   // 128 KB
__device__ float g_sum[FIN_BLOCKS];
__device__ unsigned int g_ticket;                 // zero-init; reset each call

// Monotone map: larger key  <=>  smaller float. enc(f) strictly decreasing.
__device__ __forceinline__ unsigned int enc_min(float f) {
    int b = __float_as_int(f);
    unsigned int u = (unsigned int)(b ^ ((b >> 31) | 0x80000000));
    return ~u;
}
__device__ __forceinline__ float dec_min(unsigned int k) {
    unsigned int u = ~k;
    int b = (u & 0x80000000u) ? (int)(u ^ 0x80000000u) : (int)(~u);
    return __int_as_float(b);
}

// ---------------------------------------------------------------------------
__global__ void __launch_bounds__(THREADS, 8)
chamfer_main(const float* __restrict__ p1, const float* __restrict__ p2) {
    __shared__ float4 sc[CPB];               // (-2x,-2y,-2z,|c|^2)  16 KB

    int bx = blockIdx.x;
    int b  = bx >> 7;                        // batch
    int rt = (bx >> 2) & 31;                 // row tile
    int ct = bx & 3;                         // col tile
    const float* __restrict__ rows = p1 + (b * NPTS + rt * RPB) * 3;
    const float* __restrict__ cols = p2 + (b * NPTS + ct * CPB) * 3;

    int t = threadIdx.x, w = t >> 5, lane = t & 31;

    // Stage 1024 candidates: 8 per thread via 2 groups of 3x LDG.128.
    #pragma unroll
    for (int g = 0; g < CPB / (4 * THREADS); ++g) {
        int ci = t + g * THREADS;
        const float4* s4 = (const float4*)cols + 3 * ci;
        float4 v0 = s4[0], v1 = s4[1], v2 = s4[2];
        float cx[4] = { v0.x, v0.w, v1.z, v2.y };
        float cy[4] = { v0.y, v1.x, v1.w, v2.z };
        float cz[4] = { v0.z, v1.y, v2.x, v2.w };
        #pragma unroll
        for (int k = 0; k < 4; ++k) {
            float x = cx[k], y = cy[k], z = cz[k];
            float n = fmaf(x, x, fmaf(y, y, z * z));
            sc[4 * ci + k] = make_float4(-2.0f * x, -2.0f * y, -2.0f * z, n);
        }
    }

    // 4 rows per lane (whole 128-row tile per warp).
    float rx[4], ry[4], rz[4], rn[4], rm[4];
    #pragma unroll
    for (int k = 0; k < 4; ++k) {
        int r = k * 32 + lane;
        rx[k] = rows[3 * r + 0];
        ry[k] = rows[3 * r + 1];
        rz[k] = rows[3 * r + 2];
        rn[k] = fmaf(rx[k], rx[k], fmaf(ry[k], ry[k], rz[k] * rz[k]));
        rm[k] = CUDART_INF_F;
    }
    __syncthreads();

    const char* sbase = (const char*)sc;
    #pragma unroll
    for (int cc = 0; cc < WCOLS / 32; ++cc) {            // 8 groups of 32 cols
        uint32_t off0 = (uint32_t)(w * WCOLS + cc * 32 + lane) * 16u;
        float cm = CUDART_INF_F;
        #pragma unroll 8
        for (int s = 0; s < 32; ++s) {
            float4 c = *(const float4*)(sbase + (off0 ^ ((uint32_t)s << 4)));
            float w0 = fmaf(c.x, rx[0], fmaf(c.y, ry[0], fmaf(c.z, rz[0], c.w + rn[0])));
            float w1 = fmaf(c.x, rx[1], fmaf(c.y, ry[1], fmaf(c.z, rz[1], c.w + rn[1])));
            float w2 = fmaf(c.x, rx[2], fmaf(c.y, ry[2], fmaf(c.z, rz[2], c.w + rn[2])));
            float w3 = fmaf(c.x, rx[3], fmaf(c.y, ry[3], fmaf(c.z, rz[3], c.w + rn[3])));
            rm[0] = fminf(rm[0], w0);
            rm[1] = fminf(rm[1], w1);
            rm[2] = fminf(rm[2], w2);
            rm[3] = fminf(rm[3], w3);
            float cv = fminf(fminf(w0, w1), fminf(w2, w3));
            cm = fminf(cm, __shfl_xor_sync(0xffffffffu, cv, s));
        }
        // Column (ct*1024 + w*256 + cc*32 + lane) fully reduced over this
        // block's 128 rows: merge across row-tiles with deterministic atomic.
        atomicMax(&g_colkey[b * NPTS + ct * CPB + w * WCOLS + cc * 32 + lane],
                  enc_min(cm));
    }

    // Row mins over this warp's 256 cols: merge across col-tiles and warps.
    #pragma unroll
    for (int k = 0; k < 4; ++k)
        atomicMax(&g_rowkey[b * NPTS + rt * RPB + k * 32 + lane],
                  enc_min(rm[k]));
}

// ---------------------------------------------------------------------------
// Final: thread i owns global row i and global col i. Decode keys, sum,
// reset keys to 0 (identity) for the next graph replay, ticket-reduce to out.
// ---------------------------------------------------------------------------
__global__ void chamfer_final(float* __restrict__ out) {
    __shared__ float wsum[FIN_THREADS / 32];
    __shared__ bool s_last;
    int i = blockIdx.x * FIN_THREADS + threadIdx.x;      // 0..32767

    float rmin = dec_min(g_rowkey[i]);
    float cmin = dec_min(g_colkey[i]);
    g_rowkey[i] = 0u;
    g_colkey[i] = 0u;

    float s = rmin + cmin;
    int t = threadIdx.x;
    #pragma unroll
    for (int off = 16; off > 0; off >>= 1)
        s += __shfl_down_sync(0xffffffffu, s, off);
    if ((t & 31) == 0) wsum[t >> 5] = s;
    __syncthreads();
    if (t == 0) {
        float p = 0.0f;
        #pragma unroll
        for (int ww = 0; ww < FIN_THREADS / 32; ++ww) p += wsum[ww];
        g_sum[blockIdx.x] = p;
        __threadfence();
        unsigned int v = atomicAdd(&g_ticket, 1u);
        s_last = (v == FIN_BLOCKS - 1);
    }
    __syncthreads();

    // Deterministic final: exactly one block (last to arrive) reduces the
    // fixed-order g_sum array; arithmetic order independent of which block.
    if (s_last) {
        __threadfence();
        float fs = (t < FIN_BLOCKS) ? g_sum[t] : 0.0f;
        #pragma unroll
        for (int off = 16; off > 0; off >>= 1)
            fs += __shfl_down_sync(0xffffffffu, fs, off);
        if ((t & 31) == 0) wsum[t >> 5] = fs;
        __syncthreads();
        if (t == 0) {
            float tot = 0.0f;
            #pragma unroll
            for (int ww = 0; ww < FIN_BLOCKS / 32; ++ww) tot += wsum[ww];
            out[0] = tot * (1.0f / (float)(BATCH * NPTS));
            g_ticket = 0;   // reset for next graph replay
        }
    }
}

extern "C" void kernel_launch(void* const* d_in, const int* in_sizes, int n_in,
                              void* d_out, int out_size) {
    const float* p1 = (const float*)d_in[0];
    const float* p2 = (const float*)d_in[1];
    float* out = (float*)d_out;

    chamfer_main<<<MAIN_BLOCKS, THREADS>>>(p1, p2);
    chamfer_final<<<FIN_BLOCKS, FIN_THREADS>>>(out);
}

// round 12
// speedup vs baseline: 1.5322x; 1.5322x over previous
#include <cuda_runtime.h>
#include <math_constants.h>
#include <cstdint>

// ChamferDistanceLoss, B=8, N=4096, D=3 — fused both directions.
// d(i,j) = rn_i + cn_j - 2 p1_i.p2_j computed ONCE per pair.
// Main: block = (batch, 128-row tile, 1024-col tile); partial mins to gmem.
// Reduce: 768 blocks (256 row-side, 512 col-side) + ticket-merged final.

#define NPTS 4096
#define BATCH 8
#define RPB 128
#define CPB 1024
#define RT 32
#define CT 4
#define MAIN_BLOCKS (BATCH * RT * CT)       // 1024
#define THREADS 128
#define NWARPS 4
#define WCOLS (CPB / NWARPS)                // 256
#define RED_BLOCKS 768                      // 256 row blocks + 512 col blocks
#define RED_THREADS 128

__device__ float g_rowpart[MAIN_BLOCKS * NWARPS * RPB];  // 2 MB
__device__ float g_colpart[MAIN_BLOCKS * CPB];           // 4 MB
__device__ float g_sum[RED_BLOCKS];
__device__ unsigned int g_ticket;                        // zero-init; reset each call

// ---------------------------------------------------------------------------
__global__ void __launch_bounds__(THREADS, 8)
chamfer_main(const float* __restrict__ p1, const float* __restrict__ p2) {
    __shared__ float4 sc[CPB];               // (-2x,-2y,-2z,|c|^2)  16 KB

    int bx = blockIdx.x;
    int b  = bx >> 7;                        // batch
    int rt = (bx >> 2) & 31;                 // row tile
    int ct = bx & 3;                         // col tile
    const float* __restrict__ rows = p1 + (b * NPTS + rt * RPB) * 3;
    const float* __restrict__ cols = p2 + (b * NPTS + ct * CPB) * 3;

    int t = threadIdx.x, w = t >> 5, lane = t & 31;

    // Stage 1024 candidates: 8 per thread via 2 groups of 3x LDG.128.
    #pragma unroll
    for (int g = 0; g < CPB / (4 * THREADS); ++g) {
        int ci = t + g * THREADS;
        const float4* s4 = (const float4*)cols + 3 * ci;
        float4 v0 = s4[0], v1 = s4[1], v2 = s4[2];
        float cx[4] = { v0.x, v0.w, v1.z, v2.y };
        float cy[4] = { v0.y, v1.x, v1.w, v2.z };
        float cz[4] = { v0.z, v1.y, v2.x, v2.w };
        #pragma unroll
        for (int k = 0; k < 4; ++k) {
            float x = cx[k], y = cy[k], z = cz[k];
            float n = fmaf(x, x, fmaf(y, y, z * z));
            sc[4 * ci + k] = make_float4(-2.0f * x, -2.0f * y, -2.0f * z, n);
        }
    }

    // 4 rows per lane (whole 128-row tile per warp).
    float rx[4], ry[4], rz[4], rn[4], rm[4];
    #pragma unroll
    for (int k = 0; k < 4; ++k) {
        int r = k * 32 + lane;
        rx[k] = rows[3 * r + 0];
        ry[k] = rows[3 * r + 1];
        rz[k] = rows[3 * r + 2];
        rn[k] = fmaf(rx[k], rx[k], fmaf(ry[k], ry[k], rz[k] * rz[k]));
        rm[k] = CUDART_INF_F;
    }
    __syncthreads();

    const char* sbase = (const char*)sc;
    #pragma unroll
    for (int cc = 0; cc < WCOLS / 32; ++cc) {            // 8 groups of 32 cols
        uint32_t off0 = (uint32_t)(w * WCOLS + cc * 32 + lane) * 16u;
        float cm = CUDART_INF_F;
        #pragma unroll 8
        for (int s = 0; s < 32; ++s) {
            float4 c = *(const float4*)(sbase + (off0 ^ ((uint32_t)s << 4)));
            float w0 = fmaf(c.x, rx[0], fmaf(c.y, ry[0], fmaf(c.z, rz[0], c.w + rn[0])));
            float w1 = fmaf(c.x, rx[1], fmaf(c.y, ry[1], fmaf(c.z, rz[1], c.w + rn[1])));
            float w2 = fmaf(c.x, rx[2], fmaf(c.y, ry[2], fmaf(c.z, rz[2], c.w + rn[2])));
            float w3 = fmaf(c.x, rx[3], fmaf(c.y, ry[3], fmaf(c.z, rz[3], c.w + rn[3])));
            rm[0] = fminf(rm[0], w0);
            rm[1] = fminf(rm[1], w1);
            rm[2] = fminf(rm[2], w2);
            rm[3] = fminf(rm[3], w3);
            float cv = fminf(fminf(w0, w1), fminf(w2, w3));
            cm = fminf(cm, __shfl_xor_sync(0xffffffffu, cv, s));
        }
        // This warp reduced column (base + lane) over all 128 rows: final partial.
        g_colpart[bx * CPB + w * WCOLS + cc * 32 + lane] = cm;
    }

    // Row partials: full-d min over this warp's 256 cols (rn already folded in).
    #pragma unroll
    for (int k = 0; k < 4; ++k)
        g_rowpart[(bx * NWARPS + w) * RPB + k * 32 + lane] = rm[k];
}

// ---------------------------------------------------------------------------
// Reduce (one launch, ticket-merged final):
//  blocks [0,256):   row side, thread -> one row index, min over 16 partials.
//  blocks [256,768): col side, 2 threads per column (16 partials each, shfl).
//  last block sums the fixed-order g_sum[768] -> loss.
// ---------------------------------------------------------------------------
__global__ void __launch_bounds__(RED_THREADS)
chamfer_reduce(float* __restrict__ out) {
    __shared__ float wsum[RED_THREADS / 32];
    __shared__ bool s_last;
    int bid = blockIdx.x, t = threadIdx.x;

    float s;
    if (bid < 256) {
        int i = bid * RED_THREADS + t;                   // 0..32767 row index
        int b = i >> 12;
        int r = i & (NPTS - 1);
        int rt = r >> 7, rr = r & 127;
        float rmin = CUDART_INF_F;
        #pragma unroll
        for (int c = 0; c < CT; ++c)
            #pragma unroll
            for (int ww = 0; ww < NWARPS; ++ww)
                rmin = fminf(rmin,
                    g_rowpart[(((b * RT + rt) * CT + c) * NWARPS + ww) * RPB + rr]);
        s = rmin;
    } else {
        int q = (bid - 256) * 64 + (t >> 1);             // 0..32767 col index
        int h = t & 1;                                   // half of the partial list
        int b = q >> 12;
        int cidx = q & (NPTS - 1);
        int ctile = cidx >> 10, cc = cidx & (CPB - 1);
        float cmin = CUDART_INF_F;
        #pragma unroll
        for (int k = 0; k < RT / 2; ++k) {
            int rt2 = h * (RT / 2) + k;
            cmin = fminf(cmin,
                g_colpart[((b * RT + rt2) * CT + ctile) * CPB + cc]);
        }
        cmin = fminf(cmin, __shfl_xor_sync(0xffffffffu, cmin, 1));
        s = (h == 0) ? cmin : 0.0f;
    }

    #pragma unroll
    for (int off = 16; off > 0; off >>= 1)
        s += __shfl_down_sync(0xffffffffu, s, off);
    if ((t & 31) == 0) wsum[t >> 5] = s;
    __syncthreads();
    if (t == 0) {
        float p = 0.0f;
        #pragma unroll
        for (int ww = 0; ww < RED_THREADS / 32; ++ww) p += wsum[ww];
        g_sum[bid] = p;
        __threadfence();
        unsigned int v = atomicAdd(&g_ticket, 1u);
        s_last = (v == RED_BLOCKS - 1);
    }
    __syncthreads();

    // Deterministic final: exactly one block (last to arrive) reduces the
    // fixed-order g_sum array; arithmetic order independent of which block.
    if (s_last) {
        __threadfence();
        float fs = 0.0f;
        #pragma unroll
        for (int k = 0; k < RED_BLOCKS / RED_THREADS; ++k)
            fs += g_sum[t + k * RED_THREADS];
        #pragma unroll
        for (int off = 16; off > 0; off >>= 1)
            fs += __shfl_down_sync(0xffffffffu, fs, off);
        if ((t & 31) == 0) wsum[t >> 5] = fs;
        __syncthreads();
        if (t == 0) {
            float tot = 0.0f;
            #pragma unroll
            for (int ww = 0; ww < RED_THREADS / 32; ++ww) tot += wsum[ww];
            out[0] = tot * (1.0f / (float)(BATCH * NPTS));
            g_ticket = 0;   // reset for next graph replay
        }
    }
}

extern "C" void kernel_launch(void* const* d_in, const int* in_sizes, int n_in,
                              void* d_out, int out_size) {
    const float* p1 = (const float*)d_in[0];
    const float* p2 = (const float*)d_in[1];
    float* out = (float*)d_out;

    chamfer_main<<<MAIN_BLOCKS, THREADS>>>(p1, p2);
    chamfer_reduce<<<RED_BLOCKS, RED_THREADS>>>(out);
}

// round 13
// speedup vs baseline: 1.6906x; 1.1034x over previous
#include <cuda_runtime.h>
#include <math_constants.h>
#include <cstdint>

// ChamferDistanceLoss, B=8, N=4096, D=3 — fused both directions.
// d(i,j) = rn_i + cn_j - 2 p1_i.p2_j computed ONCE per pair.
// Main: block = (batch, 256-row tile, 512-col tile) = 1024 blocks, 128 thr.
//   Each warp: 128-col slice, ALL 256 rows (8/lane). XOR rotation for the
//   col-side min (1 shfl per 256 pairs). Row partials combined across the
//   4 warps in smem before store (multiplicity 8); col partials have
//   multiplicity 16. Total partial traffic 3 MB (was 6).
// Reduce: 320 blocks (256 row-side scalar, 64 col-side LDG.128) + ticket final.

#define NPTS 4096
#define BATCH 8
#define RPB 256
#define CPB 512
#define RT 16
#define CT 8
#define MAIN_BLOCKS (BATCH * RT * CT)       // 1024
#define THREADS 128
#define NWARPS 4
#define WCOLS (CPB / NWARPS)                // 128
#define RED_BLOCKS 320                      // 256 row-side + 64 col-side
#define RED_THREADS 128

__device__ float g_rowpart[MAIN_BLOCKS * RPB];   // 1 MB  (per block: 256 rows)
__device__ float g_colpart[MAIN_BLOCKS * CPB];   // 2 MB  (per block: 512 cols)
__device__ float g_sum[RED_BLOCKS];
__device__ unsigned int g_ticket;                // zero-init; reset each call

// ---------------------------------------------------------------------------
__global__ void __launch_bounds__(THREADS, 6)
chamfer_main(const float* __restrict__ p1, const float* __restrict__ p2) {
    __shared__ float4 sc[CPB];                    // (-2x,-2y,-2z,|c|^2)  8 KB
    __shared__ float  s_row[NWARPS * RPB];        // 4 KB

    int bx = blockIdx.x;
    int b  = bx >> 7;                             // batch
    int rt = (bx >> 3) & 15;                      // row tile (256 rows)
    int ct = bx & 7;                              // col tile (512 cols)
    const float* __restrict__ rows = p1 + (b * NPTS + rt * RPB) * 3;
    const float* __restrict__ cols = p2 + (b * NPTS + ct * CPB) * 3;

    int t = threadIdx.x, w = t >> 5, lane = t & 31;

    // Stage 512 candidates: 4 per thread via 3x LDG.128 (48B per thread).
    {
        const float4* s4 = (const float4*)cols + 3 * t;
        float4 v0 = s4[0], v1 = s4[1], v2 = s4[2];
        float cx[4] = { v0.x, v0.w, v1.z, v2.y };
        float cy[4] = { v0.y, v1.x, v1.w, v2.z };
        float cz[4] = { v0.z, v1.y, v2.x, v2.w };
        #pragma unroll
        for (int k = 0; k < 4; ++k) {
            float x = cx[k], y = cy[k], z = cz[k];
            float n = fmaf(x, x, fmaf(y, y, z * z));
            sc[4 * t + k] = make_float4(-2.0f * x, -2.0f * y, -2.0f * z, n);
        }
    }

    // 8 rows per lane (whole 256-row tile per warp).
    float rx[8], ry[8], rz[8], rn[8], rm[8];
    #pragma unroll
    for (int k = 0; k < 8; ++k) {
        int r = k * 32 + lane;
        rx[k] = rows[3 * r + 0];
        ry[k] = rows[3 * r + 1];
        rz[k] = rows[3 * r + 2];
        rn[k] = fmaf(rx[k], rx[k], fmaf(ry[k], ry[k], rz[k] * rz[k]));
        rm[k] = CUDART_INF_F;                     // accumulates e = cn - 2dot
    }
    __syncthreads();

    const char* sbase = (const char*)sc;
    #pragma unroll
    for (int cc = 0; cc < WCOLS / 32; ++cc) {     // 4 groups of 32 cols
        uint32_t off0 = (uint32_t)(w * WCOLS + cc * 32 + lane) * 16u;
        float cm = CUDART_INF_F;
        #pragma unroll 8
        for (int s = 0; s < 32; ++s) {
            float4 c = *(const float4*)(sbase + (off0 ^ ((uint32_t)s << 4)));
            float e[8];
            #pragma unroll
            for (int k = 0; k < 8; ++k) {
                e[k] = fmaf(c.x, rx[k], fmaf(c.y, ry[k], fmaf(c.z, rz[k], c.w)));
                rm[k] = fminf(rm[k], e[k]);       // row side: rn added later
            }
            // col side needs full d = e + rn (rn varies across rows)
            float cv = fminf(
                fminf(fminf(e[0] + rn[0], e[1] + rn[1]),
                      fminf(e[2] + rn[2], e[3] + rn[3])),
                fminf(fminf(e[4] + rn[4], e[5] + rn[5]),
                      fminf(e[6] + rn[6], e[7] + rn[7])));
            cm = fminf(cm, __shfl_xor_sync(0xffffffffu, cv, s));
        }
        // Column (ct*512 + w*128 + cc*32 + lane) reduced over all 256 rows.
        g_colpart[bx * CPB + w * WCOLS + cc * 32 + lane] = cm;
    }

    // Row side: fold rn, then combine across the 4 warps (same rows) in smem.
    #pragma unroll
    for (int k = 0; k < 8; ++k)
        s_row[w * RPB + k * 32 + lane] = rn[k] + rm[k];
    __syncthreads();
    #pragma unroll
    for (int rr = t; rr < RPB; rr += THREADS) {
        float v = fminf(fminf(s_row[rr], s_row[RPB + rr]),
                        fminf(s_row[2 * RPB + rr], s_row[3 * RPB + rr]));
        g_rowpart[bx * RPB + rr] = v;
    }
}

// ---------------------------------------------------------------------------
// Reduce (one launch, ticket-merged final):
//  blocks [0,256):   row side — thread -> one row, min over 8 partials (ct).
//  blocks [256,320): col side — thread -> 4 cols (float4), min over 16 (rt).
//  last block sums the fixed-order g_sum[320] -> loss.
// ---------------------------------------------------------------------------
__global__ void __launch_bounds__(RED_THREADS)
chamfer_reduce(float* __restrict__ out) {
    __shared__ float wsum[RED_THREADS / 32];
    __shared__ bool s_last;
    int bid = blockIdx.x, t = threadIdx.x;

    float s;
    if (bid < 256) {
        int i = bid * RED_THREADS + t;            // 0..32767 row index
        int b = i >> 12;
        int r = i & (NPTS - 1);
        int rt = r >> 8, rr = r & (RPB - 1);
        float rmin = CUDART_INF_F;
        #pragma unroll
        for (int c = 0; c < CT; ++c)
            rmin = fminf(rmin,
                g_rowpart[((b * RT + rt) * CT + c) * RPB + rr]);
        s = rmin;
    } else {
        int q = (bid - 256) * RED_THREADS + t;    // 0..8191 col-quad index
        int b = q >> 10;
        int g4 = q & 1023;
        int ct = g4 >> 7;
        int cc4 = (g4 & 127) * 4;
        float4 acc = make_float4(CUDART_INF_F, CUDART_INF_F,
                                 CUDART_INF_F, CUDART_INF_F);
        #pragma unroll
        for (int rt = 0; rt < RT; ++rt) {
            const float4 v = *(const float4*)
                &g_colpart[((b * RT + rt) * CT + ct) * CPB + cc4];
            acc.x = fminf(acc.x, v.x);
            acc.y = fminf(acc.y, v.y);
            acc.z = fminf(acc.z, v.z);
            acc.w = fminf(acc.w, v.w);
        }
        s = (acc.x + acc.y) + (acc.z + acc.w);
    }

    #pragma unroll
    for (int off = 16; off > 0; off >>= 1)
        s += __shfl_down_sync(0xffffffffu, s, off);
    if ((t & 31) == 0) wsum[t >> 5] = s;
    __syncthreads();
    if (t == 0) {
        float p = 0.0f;
        #pragma unroll
        for (int ww = 0; ww < RED_THREADS / 32; ++ww) p += wsum[ww];
        g_sum[bid] = p;
        __threadfence();
        unsigned int v = atomicAdd(&g_ticket, 1u);
        s_last = (v == RED_BLOCKS - 1);
    }
    __syncthreads();

    // Deterministic final: exactly one block (last to arrive) reduces the
    // fixed-order g_sum array; arithmetic order independent of which block.
    if (s_last) {
        __threadfence();
        float fs = g_sum[t] + g_sum[t + 128] + ((t < 64) ? g_sum[t + 256] : 0.0f);
        #pragma unroll
        for (int off = 16; off > 0; off >>= 1)
            fs += __shfl_down_sync(0xffffffffu, fs, off);
        if ((t & 31) == 0) wsum[t >> 5] = fs;
        __syncthreads();
        if (t == 0) {
            float tot = 0.0f;
            #pragma unroll
            for (int ww = 0; ww < RED_THREADS / 32; ++ww) tot += wsum[ww];
            out[0] = tot * (1.0f / (float)(BATCH * NPTS));
            g_ticket = 0;   // reset for next graph replay
        }
    }
}

extern "C" void kernel_launch(void* const* d_in, const int* in_sizes, int n_in,
                              void* d_out, int out_size) {
    const float* p1 = (const float*)d_in[0];
    const float* p2 = (const float*)d_in[1];
    float* out = (float*)d_out;

    chamfer_main<<<MAIN_BLOCKS, THREADS>>>(p1, p2);
    chamfer_reduce<<<RED_BLOCKS, RED_THREADS>>>(out);
}